// round 2
// baseline (speedup 1.0000x reference)
#include <cuda_runtime.h>
#include <math.h>

#define Dm   1024
#define Hh   16
#define DH   64
#define Bb   8
#define Tt   128
#define TEe  256
#define Nn   1024      /* B*T  */
#define NE2  2048      /* B*TE */
#define Ee   8
#define HIDf 4096
#define KCB  8192
#define NLAY 2

// -------------------- static scratch (no allocations allowed) --------------------
__device__ float d_x  [Nn * Dm];
__device__ float d_nb [Nn * Dm];
__device__ float d_q  [Nn * Dm];
__device__ float d_k  [NE2 * Dm];
__device__ float d_v  [NE2 * Dm];
__device__ float d_att[Nn * Dm];
__device__ float d_g  [(long)Ee * Nn * HIDf];   // 134 MB: gate -> silu(g)*u in place
__device__ float d_ob [(long)Ee * Nn * Dm];     // 32 MB: per-expert down outputs
__device__ float d_wex[Nn * Ee];                // gating weights (zeros except top-2)

// -------------------- helpers --------------------
__device__ __forceinline__ float block_reduce(float v, bool do_max)
{
    __shared__ float sh[8];
    int lane = threadIdx.x & 31, w = threadIdx.x >> 5;
    int nw = blockDim.x >> 5;
#pragma unroll
    for (int o = 16; o; o >>= 1) {
        float u = __shfl_xor_sync(0xffffffffu, v, o);
        v = do_max ? fmaxf(v, u) : v + u;
    }
    __syncthreads();          // protect sh reuse across successive calls
    if (lane == 0) sh[w] = v;
    __syncthreads();
    float r = sh[0];
    for (int i = 1; i < nw; i++) r = do_max ? fmaxf(r, sh[i]) : r + sh[i];
    return r;
}

// -------------------- embedding --------------------
__global__ void embed_kernel(const int* __restrict__ ids,
                             const float* __restrict__ emb,
                             float* __restrict__ x)
{
    int i = blockIdx.x * 256 + threadIdx.x;    // over Nn*Dm/4 float4
    int n = i >> 8;                            // Dm/4 = 256
    int c = i & 255;
    ((float4*)x)[i] = ((const float4*)emb)[(long)ids[n] * 256 + c];
}

// -------------------- rmsnorm --------------------
__global__ void rms_kernel(const float* __restrict__ X,
                           const float* __restrict__ W,
                           float* __restrict__ Y)
{
    int n = blockIdx.x, tid = threadIdx.x;     // 256 threads, one float4 each
    float4 x4 = ((const float4*)X)[n * 256 + tid];
    float ss = x4.x * x4.x + x4.y * x4.y + x4.z * x4.z + x4.w * x4.w;
    float tot = block_reduce(ss, false);
    float sc = rsqrtf(tot * (1.0f / 1024.0f) + 1e-6f);
    float4 w4 = ((const float4*)W)[tid];
    float4 y;
    y.x = x4.x * sc * w4.x; y.y = x4.y * sc * w4.y;
    y.z = x4.z * sc * w4.z; y.w = x4.w * sc * w4.w;
    ((float4*)Y)[n * 256 + tid] = y;
}

// -------------------- GEMM: C[N,M] = A[N,K] * B[M,K]^T --------------------
// MODE 0: store   MODE 1: C += acc   MODE 2: C = silu(G) * acc  (G may == C)
template <int BN, int MODE>
__global__ void __launch_bounds__(256, 2)
gemm_nt(const float* __restrict__ A, const float* __restrict__ Bm,
        float* C, const float* G,
        int K, int M, long azs, long bzs, long czs)
{
    constexpr int BM = 128, BK = 16;
    constexpr int TN = BN / 16;                // 8 or 4
    const int z = blockIdx.z;
    A  += (long)z * azs;
    Bm += (long)z * bzs;
    C  += (long)z * czs;
    const float* Gp = (MODE == 2) ? (G + (long)z * czs) : nullptr;

    __shared__ __align__(16) float As[BK][BM + 4];
    __shared__ __align__(16) float Bs[BK][BN + 4];

    const int tid = threadIdx.x;
    const long rowBase = (long)blockIdx.y * BM;
    const long colBase = (long)blockIdx.x * BN;
    const int lr = tid >> 2;          // 0..63
    const int lc = (tid & 3) * 4;     // 0,4,8,12
    const float* Ag = A  + (rowBase + lr) * K + lc;
    const float* Bg = Bm + (colBase + lr) * K + lc;

    float4 ra0, ra1, rb0, rb1;
    ra0 = *(const float4*)(Ag);
    ra1 = *(const float4*)(Ag + 64l * K);
    rb0 = *(const float4*)(Bg);
    if (BN == 128) rb1 = *(const float4*)(Bg + 64l * K);

    float acc[8][TN];
#pragma unroll
    for (int i = 0; i < 8; i++)
#pragma unroll
        for (int j = 0; j < TN; j++) acc[i][j] = 0.f;

    const int tx = tid & 15;
    const int ty = tid >> 4;

    for (int k0 = 0; k0 < K; k0 += BK) {
        // store prefetched tile
        As[lc + 0][lr] = ra0.x; As[lc + 1][lr] = ra0.y;
        As[lc + 2][lr] = ra0.z; As[lc + 3][lr] = ra0.w;
        As[lc + 0][lr + 64] = ra1.x; As[lc + 1][lr + 64] = ra1.y;
        As[lc + 2][lr + 64] = ra1.z; As[lc + 3][lr + 64] = ra1.w;
        Bs[lc + 0][lr] = rb0.x; Bs[lc + 1][lr] = rb0.y;
        Bs[lc + 2][lr] = rb0.z; Bs[lc + 3][lr] = rb0.w;
        if (BN == 128) {
            Bs[lc + 0][lr + 64] = rb1.x; Bs[lc + 1][lr + 64] = rb1.y;
            Bs[lc + 2][lr + 64] = rb1.z; Bs[lc + 3][lr + 64] = rb1.w;
        }
        __syncthreads();
        bool more = (k0 + BK) < K;
        if (more) {
            ra0 = *(const float4*)(Ag + (k0 + BK));
            ra1 = *(const float4*)(Ag + 64l * K + (k0 + BK));
            rb0 = *(const float4*)(Bg + (k0 + BK));
            if (BN == 128) rb1 = *(const float4*)(Bg + 64l * K + (k0 + BK));
        }
#pragma unroll
        for (int kk = 0; kk < BK; kk++) {
            float4 a0 = *(const float4*)&As[kk][ty * 8];
            float4 a1 = *(const float4*)&As[kk][ty * 8 + 4];
            float4 b0 = *(const float4*)&Bs[kk][tx * TN];
            float av[8] = {a0.x, a0.y, a0.z, a0.w, a1.x, a1.y, a1.z, a1.w};
            float bv[8];
            bv[0] = b0.x; bv[1] = b0.y; bv[2] = b0.z; bv[3] = b0.w;
            if (BN == 128) {
                float4 b1 = *(const float4*)&Bs[kk][tx * TN + 4];
                bv[4] = b1.x; bv[5] = b1.y; bv[6] = b1.z; bv[7] = b1.w;
            }
#pragma unroll
            for (int i = 0; i < 8; i++)
#pragma unroll
                for (int j = 0; j < TN; j++)
                    acc[i][j] += av[i] * bv[j];
        }
        __syncthreads();
    }

    // epilogue (vectorized)
#pragma unroll
    for (int i = 0; i < 8; i++) {
        long n = rowBase + ty * 8 + i;
        float*       Crow = C  + n * M + colBase + tx * TN;
        const float* Grow = (MODE == 2) ? (Gp + n * M + colBase + tx * TN) : nullptr;
#pragma unroll
        for (int j4 = 0; j4 < TN / 4; j4++) {
            float4 r;
            r.x = acc[i][j4 * 4 + 0]; r.y = acc[i][j4 * 4 + 1];
            r.z = acc[i][j4 * 4 + 2]; r.w = acc[i][j4 * 4 + 3];
            if (MODE == 0) {
                ((float4*)Crow)[j4] = r;
            } else if (MODE == 1) {
                float4 c = ((float4*)Crow)[j4];
                c.x += r.x; c.y += r.y; c.z += r.z; c.w += r.w;
                ((float4*)Crow)[j4] = c;
            } else {
                float4 gg = ((const float4*)Grow)[j4];
                r.x *= gg.x / (1.f + expf(-gg.x));
                r.y *= gg.y / (1.f + expf(-gg.y));
                r.z *= gg.z / (1.f + expf(-gg.z));
                r.w *= gg.w / (1.f + expf(-gg.w));
                ((float4*)Crow)[j4] = r;
            }
        }
    }
}

// -------------------- attention: one block per (b,h,t) query --------------------
__global__ void attn_kernel(const float* __restrict__ Q, const float* __restrict__ K,
                            const float* __restrict__ V, float* __restrict__ O,
                            int Tk, int kvS, int causal)
{
    const int t = blockIdx.x, h = blockIdx.y, b = blockIdx.z;
    const int tid = threadIdx.x;                 // 128 threads
    __shared__ float qs[DH];
    __shared__ float sc[TEe];
    __shared__ float oacc[2][DH];

    const long qoff = (long)(b * Tt + t) * Dm + h * DH;
    if (tid < DH) qs[tid] = Q[qoff + tid];
    __syncthreads();

    float lmax = -1e30f;
    for (int kk = tid; kk < Tk; kk += 128) {
        float s;
        if (causal && kk > t) {
            s = -1e30f;
        } else {
            const float* kr = K + (long)(b * kvS + kk) * Dm + h * DH;
            s = 0.f;
#pragma unroll
            for (int d = 0; d < DH; d++) s += qs[d] * kr[d];
            s *= 0.125f;                          // dh^-0.5
        }
        sc[kk] = s;
        lmax = fmaxf(lmax, s);
    }
    float m = block_reduce(lmax, true);
    float lsum = 0.f;
    for (int kk = tid; kk < Tk; kk += 128) {
        float p = expf(sc[kk] - m);
        sc[kk] = p;
        lsum += p;
    }
    float ssum = block_reduce(lsum, false);       // includes syncthreads -> sc visible
    float inv = 1.0f / ssum;

    // O accumulation: 128 threads = 64 dims x 2 key-range partitions
    {
        int d    = tid & 63;
        int part = tid >> 6;            // 0 or 1
        int half = Tk >> 1;
        int k0   = part * half;
        float acc = 0.f;
        const float* vb = V + (long)(b * kvS + k0) * Dm + h * DH + d;
        for (int kk = 0; kk < half; kk++)
            acc += sc[k0 + kk] * vb[(long)kk * Dm];
        oacc[part][d] = acc;
    }
    __syncthreads();
    if (tid < DH)
        O[qoff + tid] = (oacc[0][tid] + oacc[1][tid]) * inv;
}

// -------------------- router: top-2 softmax gate weights --------------------
__global__ void router_kernel(const float* __restrict__ X,
                              const float* __restrict__ RW,
                              float* __restrict__ Wout)
{
    int n = blockIdx.x, tid = threadIdx.x;       // 256 threads = 8 warps
    int e = tid >> 5, lane = tid & 31;
    __shared__ float lg[Ee];
    const float4* xr = (const float4*)(X + (long)n * Dm);
    const float4* wr = (const float4*)(RW + (long)e * Dm);
    float s = 0.f;
    for (int i = lane; i < 256; i += 32) {
        float4 a = xr[i], b = wr[i];
        s += a.x * b.x + a.y * b.y + a.z * b.z + a.w * b.w;
    }
#pragma unroll
    for (int o = 16; o; o >>= 1) s += __shfl_xor_sync(0xffffffffu, s, o);
    if (lane == 0) lg[e] = s;
    __syncthreads();
    if (tid == 0) {
        int i1 = 0; float m1 = lg[0];
        for (int i = 1; i < Ee; i++) if (lg[i] > m1) { m1 = lg[i]; i1 = i; }
        int i2 = -1; float m2 = -1e30f;
        for (int i = 0; i < Ee; i++) if (i != i1 && lg[i] > m2) { m2 = lg[i]; i2 = i; }
        float w1 = 1.0f / (1.0f + expf(m2 - m1));
        float w2 = 1.0f - w1;
        for (int i = 0; i < Ee; i++) Wout[n * Ee + i] = 0.0f;
        Wout[n * Ee + i1] = w1;
        Wout[n * Ee + i2] = w2;
    }
}

// -------------------- MoE weighted reduce: x += sum_e w[n,e] * ob[e,n,:] --------------------
__global__ void moe_reduce_kernel(const float* __restrict__ Ob,
                                  const float* __restrict__ Wg,
                                  float* __restrict__ X)
{
    int i = blockIdx.x * 256 + threadIdx.x;      // float4 over Nn*Dm/4
    int n = i >> 8;
    float4 acc = ((float4*)X)[i];
#pragma unroll
    for (int e = 0; e < Ee; e++) {
        float w = Wg[n * Ee + e];
        float4 o4 = ((const float4*)Ob)[(long)e * (Nn * Dm / 4) + i];
        acc.x += w * o4.x; acc.y += w * o4.y;
        acc.z += w * o4.z; acc.w += w * o4.w;
    }
    ((float4*)X)[i] = acc;
}

// -------------------- host orchestration --------------------
static inline void launch_gemm(int mode, int bn, const float* A, const float* Bw,
                               float* C, const float* G, int Nrows, int M, int K,
                               int zc, long azs, long bzs, long czs)
{
    dim3 grid(M / bn, Nrows / 128, zc);
    dim3 blk(256);
    if (bn == 128) {
        if (mode == 0)      gemm_nt<128, 0><<<grid, blk>>>(A, Bw, C, G, K, M, azs, bzs, czs);
        else                gemm_nt<128, 2><<<grid, blk>>>(A, Bw, C, G, K, M, azs, bzs, czs);
    } else {
        if (mode == 0)      gemm_nt<64, 0><<<grid, blk>>>(A, Bw, C, G, K, M, azs, bzs, czs);
        else                gemm_nt<64, 1><<<grid, blk>>>(A, Bw, C, G, K, M, azs, bzs, czs);
    }
}

extern "C" void kernel_launch(void* const* d_in, const int* in_sizes, int n_in,
                              void* d_out, int out_size)
{
    const int*   ids = (const int*)d_in[0];
    const float* enc = (const float*)d_in[1];
    const float* emb = (const float*)d_in[2];
    const float* nw1 = (const float*)d_in[3];
    const float* nw2 = (const float*)d_in[4];
    const float* nw3 = (const float*)d_in[5];
    const float* wqs = (const float*)d_in[6];
    const float* wks = (const float*)d_in[7];
    const float* wvs = (const float*)d_in[8];
    const float* wos = (const float*)d_in[9];
    const float* wqc = (const float*)d_in[10];
    const float* wkc = (const float*)d_in[11];
    const float* wvc = (const float*)d_in[12];
    const float* woc = (const float*)d_in[13];
    const float* rw  = (const float*)d_in[14];
    const float* wg  = (const float*)d_in[15];
    const float* wu  = (const float*)d_in[16];
    const float* wd  = (const float*)d_in[17];
    const float* fnw = (const float*)d_in[18];
    const float* hw  = (const float*)d_in[19];
    float* out = (float*)d_out;

    float *x, *nb, *q, *k, *v, *att, *g, *ob, *wex;
    cudaGetSymbolAddress((void**)&x,   d_x);
    cudaGetSymbolAddress((void**)&nb,  d_nb);
    cudaGetSymbolAddress((void**)&q,   d_q);
    cudaGetSymbolAddress((void**)&k,   d_k);
    cudaGetSymbolAddress((void**)&v,   d_v);
    cudaGetSymbolAddress((void**)&att, d_att);
    cudaGetSymbolAddress((void**)&g,   d_g);
    cudaGetSymbolAddress((void**)&ob,  d_ob);
    cudaGetSymbolAddress((void**)&wex, d_wex);

    const long DD = (long)Dm * Dm;

    embed_kernel<<<Nn * Dm / 4 / 256, 256>>>(ids, emb, x);

    for (int l = 0; l < NLAY; l++) {
        // ---- self attention ----
        rms_kernel<<<Nn, 256>>>(x, nw1 + l * Dm, nb);
        launch_gemm(0, 64, nb, wqs + l * DD, q, nullptr, Nn, Dm, Dm, 1, 0, 0, 0);
        launch_gemm(0, 64, nb, wks + l * DD, k, nullptr, Nn, Dm, Dm, 1, 0, 0, 0);
        launch_gemm(0, 64, nb, wvs + l * DD, v, nullptr, Nn, Dm, Dm, 1, 0, 0, 0);
        attn_kernel<<<dim3(Tt, Hh, Bb), 128>>>(q, k, v, att, Tt, Tt, 1);
        launch_gemm(1, 64, att, wos + l * DD, x, nullptr, Nn, Dm, Dm, 1, 0, 0, 0);

        // ---- cross attention ----
        rms_kernel<<<Nn, 256>>>(x, nw2 + l * Dm, nb);
        launch_gemm(0, 64, nb,  wqc + l * DD, q, nullptr, Nn,  Dm, Dm, 1, 0, 0, 0);
        launch_gemm(0, 64, enc, wkc + l * DD, k, nullptr, NE2, Dm, Dm, 1, 0, 0, 0);
        launch_gemm(0, 64, enc, wvc + l * DD, v, nullptr, NE2, Dm, Dm, 1, 0, 0, 0);
        attn_kernel<<<dim3(Tt, Hh, Bb), 128>>>(q, k, v, att, TEe, TEe, 0);
        launch_gemm(1, 64, att, woc + l * DD, x, nullptr, Nn, Dm, Dm, 1, 0, 0, 0);

        // ---- MoE ----
        rms_kernel<<<Nn, 256>>>(x, nw3 + l * Dm, nb);
        router_kernel<<<Nn, 256>>>(nb, rw + (long)l * Ee * Dm, wex);
        // gate: g[e] = nb @ w_gate[l,e]^T  (batched over experts via gridDim.z)
        launch_gemm(0, 128, nb, wg + (long)l * Ee * HIDf * Dm, g, nullptr,
                    Nn, HIDf, Dm, Ee, 0, (long)HIDf * Dm, (long)Nn * HIDf);
        // up with epilogue: g[e] = silu(g[e]) * (nb @ w_up[l,e]^T)   (in place)
        launch_gemm(2, 128, nb, wu + (long)l * Ee * HIDf * Dm, g, g,
                    Nn, HIDf, Dm, Ee, 0, (long)HIDf * Dm, (long)Nn * HIDf);
        // down: ob[e] = g[e] @ w_down[l,e]^T
        launch_gemm(0, 64, g, wd + (long)l * Ee * Dm * HIDf, ob, nullptr,
                    Nn, Dm, HIDf, Ee, (long)Nn * HIDf, (long)Dm * HIDf, (long)Nn * Dm);
        moe_reduce_kernel<<<Nn * Dm / 4 / 256, 256>>>(ob, wex, x);
    }

    // ---- final norm + heads ----
    rms_kernel<<<Nn, 256>>>(x, fnw, nb);
    for (int lev = 0; lev < 3; lev++)
        launch_gemm(0, 128, nb, hw + (long)lev * KCB * Dm,
                    out + (long)lev * Nn * KCB, nullptr, Nn, KCB, Dm, 1, 0, 0, 0);
}

// round 5
// speedup vs baseline: 1.7971x; 1.7971x over previous
#include <cuda_runtime.h>
#include <math.h>

#define Dm   1024
#define Hh   16
#define DH   64
#define Bb   8
#define Tt   128
#define TEe  256
#define Nn   1024      /* B*T  */
#define NE2  2048      /* B*TE */
#define Ee   8
#define HIDf 4096
#define KCB  8192
#define NLAY 2

// -------------------- static scratch (no allocations allowed) --------------------
__device__ float d_x  [Nn * Dm];
__device__ float d_nb [Nn * Dm];
__device__ float d_q  [Nn * Dm];
__device__ float d_k  [NE2 * Dm];
__device__ float d_v  [NE2 * Dm];
__device__ float d_att[Nn * Dm];
__device__ float d_g  [(long)Ee * Nn * HIDf];   // gate -> silu(g)*u in place
__device__ float d_ob [(long)Ee * Nn * Dm];     // per-expert down outputs
__device__ float d_wex[Nn * Ee];                // gating weights

// -------------------- helpers --------------------
__device__ __forceinline__ float block_reduce(float v, bool do_max)
{
    __shared__ float sh[8];
    int lane = threadIdx.x & 31, w = threadIdx.x >> 5;
    int nw = blockDim.x >> 5;
#pragma unroll
    for (int o = 16; o; o >>= 1) {
        float u = __shfl_xor_sync(0xffffffffu, v, o);
        v = do_max ? fmaxf(v, u) : v + u;
    }
    __syncthreads();
    if (lane == 0) sh[w] = v;
    __syncthreads();
    float r = sh[0];
    for (int i = 1; i < nw; i++) r = do_max ? fmaxf(r, sh[i]) : r + sh[i];
    return r;
}

__device__ __forceinline__ unsigned f2tf(float f)
{
    unsigned u;
    asm("cvt.rna.tf32.f32 %0, %1;" : "=r"(u) : "f"(f));
    return u;
}

// -------------------- embedding --------------------
__global__ void embed_kernel(const int* __restrict__ ids,
                             const float* __restrict__ emb,
                             float* __restrict__ x)
{
    int i = blockIdx.x * 256 + threadIdx.x;
    int n = i >> 8;
    int c = i & 255;
    ((float4*)x)[i] = ((const float4*)emb)[(long)ids[n] * 256 + c];
}

// -------------------- rmsnorm --------------------
__global__ void rms_kernel(const float* __restrict__ X,
                           const float* __restrict__ W,
                           float* __restrict__ Y)
{
    int n = blockIdx.x, tid = threadIdx.x;
    float4 x4 = ((const float4*)X)[n * 256 + tid];
    float ss = x4.x * x4.x + x4.y * x4.y + x4.z * x4.z + x4.w * x4.w;
    float tot = block_reduce(ss, false);
    float sc = rsqrtf(tot * (1.0f / 1024.0f) + 1e-6f);
    float4 w4 = ((const float4*)W)[tid];
    float4 y;
    y.x = x4.x * sc * w4.x; y.y = x4.y * sc * w4.y;
    y.z = x4.z * sc * w4.z; y.w = x4.w * sc * w4.w;
    ((float4*)Y)[n * 256 + tid] = y;
}

// -------------------- TF32 tensor-core GEMM: C[N,M] = A[N,K] * B[M,K]^T --------------------
// MODE 0: store   MODE 1: C += acc   MODE 2: C = silu(G) * acc  (G may alias C)
template <int BN, int MODE>
__global__ void __launch_bounds__(256)
gemm_tf32(const float* __restrict__ A, const float* __restrict__ Bm,
          float* C, const float* G, int K, int M,
          long azs, long bzs, long czs)
{
    constexpr int BM = 128, BK = 16;
    constexpr int LDSs = 20;              // padded smem row stride (floats): conflict-free
    constexpr int WN = BN / 4;            // warp tile N (32 or 16)
    constexpr int NT = WN / 8;            // n-tiles per warp (4 or 2)

    const int z = blockIdx.z;
    A  += (long)z * azs;
    Bm += (long)z * bzs;
    C  += (long)z * czs;
    const float* Gp = (MODE == 2) ? (G + (long)z * czs) : nullptr;

    __shared__ __align__(16) unsigned As[BM * LDSs];
    __shared__ __align__(16) unsigned Bs[BN * LDSs];

    const int tid  = threadIdx.x;
    const int lane = tid & 31;
    const int wid  = tid >> 5;
    const int warpM = wid & 1;            // 2 warps along M
    const int warpN = wid >> 1;           // 4 warps along N
    const int gid  = lane >> 2;           // 0..7
    const int tig  = lane & 3;            // 0..3

    const long rowBase = (long)blockIdx.y * BM;
    const long colBase = (long)blockIdx.x * BN;

    const int lr = tid >> 2;              // 0..63
    const int lc = (tid & 3) * 4;         // 0,4,8,12
    const float* Ag = A  + (rowBase + lr) * K + lc;
    const float* Bg = Bm + (colBase + lr) * K + lc;

    float4 ra0, ra1, rb0, rb1;
    ra0 = *(const float4*)(Ag);
    ra1 = *(const float4*)(Ag + 64l * K);
    rb0 = *(const float4*)(Bg);
    if (BN == 128) rb1 = *(const float4*)(Bg + 64l * K);

    float acc[4][NT][4];
#pragma unroll
    for (int i = 0; i < 4; i++)
#pragma unroll
        for (int j = 0; j < NT; j++)
#pragma unroll
            for (int q = 0; q < 4; q++) acc[i][j][q] = 0.f;

    for (int k0 = 0; k0 < K; k0 += BK) {
        // convert to tf32 and store tiles
        {
            uint4 t;
            t.x = f2tf(ra0.x); t.y = f2tf(ra0.y); t.z = f2tf(ra0.z); t.w = f2tf(ra0.w);
            *(uint4*)&As[lr * LDSs + lc] = t;
            t.x = f2tf(ra1.x); t.y = f2tf(ra1.y); t.z = f2tf(ra1.z); t.w = f2tf(ra1.w);
            *(uint4*)&As[(lr + 64) * LDSs + lc] = t;
            t.x = f2tf(rb0.x); t.y = f2tf(rb0.y); t.z = f2tf(rb0.z); t.w = f2tf(rb0.w);
            *(uint4*)&Bs[lr * LDSs + lc] = t;
            if (BN == 128) {
                t.x = f2tf(rb1.x); t.y = f2tf(rb1.y); t.z = f2tf(rb1.z); t.w = f2tf(rb1.w);
                *(uint4*)&Bs[(lr + 64) * LDSs + lc] = t;
            }
        }
        __syncthreads();

        if (k0 + BK < K) {
            ra0 = *(const float4*)(Ag + (k0 + BK));
            ra1 = *(const float4*)(Ag + 64l * K + (k0 + BK));
            rb0 = *(const float4*)(Bg + (k0 + BK));
            if (BN == 128) rb1 = *(const float4*)(Bg + 64l * K + (k0 + BK));
        }

#pragma unroll
        for (int ks = 0; ks < 2; ks++) {
            const int kb = ks * 8;
            unsigned af[4][4];
            unsigned bf[NT][2];
#pragma unroll
            for (int mt = 0; mt < 4; mt++) {
                int r = warpM * 64 + mt * 16 + gid;
                af[mt][0] = As[r * LDSs + kb + tig];
                af[mt][1] = As[(r + 8) * LDSs + kb + tig];
                af[mt][2] = As[r * LDSs + kb + tig + 4];
                af[mt][3] = As[(r + 8) * LDSs + kb + tig + 4];
            }
#pragma unroll
            for (int nt = 0; nt < NT; nt++) {
                int cn = warpN * WN + nt * 8 + gid;
                bf[nt][0] = Bs[cn * LDSs + kb + tig];
                bf[nt][1] = Bs[cn * LDSs + kb + tig + 4];
            }
#pragma unroll
            for (int mt = 0; mt < 4; mt++)
#pragma unroll
                for (int nt = 0; nt < NT; nt++) {
                    asm volatile(
                        "mma.sync.aligned.m16n8k8.row.col.f32.tf32.tf32.f32 "
                        "{%0,%1,%2,%3}, {%4,%5,%6,%7}, {%8,%9}, {%0,%1,%2,%3};\n"
                        : "+f"(acc[mt][nt][0]), "+f"(acc[mt][nt][1]),
                          "+f"(acc[mt][nt][2]), "+f"(acc[mt][nt][3])
                        : "r"(af[mt][0]), "r"(af[mt][1]), "r"(af[mt][2]), "r"(af[mt][3]),
                          "r"(bf[nt][0]), "r"(bf[nt][1]));
                }
        }
        __syncthreads();
    }

    // epilogue: each lane owns 2x2 per mma tile -> float2 stores
#pragma unroll
    for (int mt = 0; mt < 4; mt++) {
        long r0 = rowBase + warpM * 64 + mt * 16 + gid;
#pragma unroll
        for (int nt = 0; nt < NT; nt++) {
            long c = colBase + warpN * WN + nt * 8 + tig * 2;
            float* p0 = C + r0 * M + c;
            float* p1 = C + (r0 + 8) * M + c;
            float2 v0 = make_float2(acc[mt][nt][0], acc[mt][nt][1]);
            float2 v1 = make_float2(acc[mt][nt][2], acc[mt][nt][3]);
            if (MODE == 0) {
                *(float2*)p0 = v0;
                *(float2*)p1 = v1;
            } else if (MODE == 1) {
                float2 o0 = *(float2*)p0, o1 = *(float2*)p1;
                o0.x += v0.x; o0.y += v0.y; o1.x += v1.x; o1.y += v1.y;
                *(float2*)p0 = o0;
                *(float2*)p1 = o1;
            } else {
                const float2 g0 = *(const float2*)(Gp + r0 * M + c);
                const float2 g1 = *(const float2*)(Gp + (r0 + 8) * M + c);
                v0.x *= g0.x / (1.f + expf(-g0.x));
                v0.y *= g0.y / (1.f + expf(-g0.y));
                v1.x *= g1.x / (1.f + expf(-g1.x));
                v1.y *= g1.y / (1.f + expf(-g1.y));
                *(float2*)p0 = v0;
                *(float2*)p1 = v1;
            }
        }
    }
}

// -------------------- attention: one block per (b,h,t) query --------------------
__global__ void attn_kernel(const float* __restrict__ Q, const float* __restrict__ K,
                            const float* __restrict__ V, float* __restrict__ O,
                            int Tk, int kvS, int causal)
{
    const int t = blockIdx.x, h = blockIdx.y, b = blockIdx.z;
    const int tid = threadIdx.x;                 // 128 threads
    __shared__ float qs[DH];
    __shared__ float sc[TEe];
    __shared__ float oacc[2][DH];

    const long qoff = (long)(b * Tt + t) * Dm + h * DH;
    if (tid < DH) qs[tid] = Q[qoff + tid];
    __syncthreads();

    float lmax = -1e30f;
    for (int kk = tid; kk < Tk; kk += 128) {
        float s;
        if (causal && kk > t) {
            s = -1e30f;
        } else {
            const float* kr = K + (long)(b * kvS + kk) * Dm + h * DH;
            s = 0.f;
#pragma unroll
            for (int d = 0; d < DH; d++) s += qs[d] * kr[d];
            s *= 0.125f;
        }
        sc[kk] = s;
        lmax = fmaxf(lmax, s);
    }
    float m = block_reduce(lmax, true);
    float lsum = 0.f;
    for (int kk = tid; kk < Tk; kk += 128) {
        float p = expf(sc[kk] - m);
        sc[kk] = p;
        lsum += p;
    }
    float ssum = block_reduce(lsum, false);
    float inv = 1.0f / ssum;

    {
        int d    = tid & 63;
        int part = tid >> 6;
        int half = Tk >> 1;
        int k0   = part * half;
        float acc = 0.f;
        const float* vb = V + (long)(b * kvS + k0) * Dm + h * DH + d;
        for (int kk = 0; kk < half; kk++)
            acc += sc[k0 + kk] * vb[(long)kk * Dm];
        oacc[part][d] = acc;
    }
    __syncthreads();
    if (tid < DH)
        O[qoff + tid] = (oacc[0][tid] + oacc[1][tid]) * inv;
}

// -------------------- router: top-2 softmax gate weights --------------------
__global__ void router_kernel(const float* __restrict__ X,
                              const float* __restrict__ RW,
                              float* __restrict__ Wout)
{
    int n = blockIdx.x, tid = threadIdx.x;
    int e = tid >> 5, lane = tid & 31;
    __shared__ float lg[Ee];
    const float4* xr = (const float4*)(X + (long)n * Dm);
    const float4* wr = (const float4*)(RW + (long)e * Dm);
    float s = 0.f;
    for (int i = lane; i < 256; i += 32) {
        float4 a = xr[i], b = wr[i];
        s += a.x * b.x + a.y * b.y + a.z * b.z + a.w * b.w;
    }
#pragma unroll
    for (int o = 16; o; o >>= 1) s += __shfl_xor_sync(0xffffffffu, s, o);
    if (lane == 0) lg[e] = s;
    __syncthreads();
    if (tid == 0) {
        int i1 = 0; float m1 = lg[0];
        for (int i = 1; i < Ee; i++) if (lg[i] > m1) { m1 = lg[i]; i1 = i; }
        int i2 = -1; float m2 = -1e30f;
        for (int i = 0; i < Ee; i++) if (i != i1 && lg[i] > m2) { m2 = lg[i]; i2 = i; }
        float w1 = 1.0f / (1.0f + expf(m2 - m1));
        float w2 = 1.0f - w1;
        for (int i = 0; i < Ee; i++) Wout[n * Ee + i] = 0.0f;
        Wout[n * Ee + i1] = w1;
        Wout[n * Ee + i2] = w2;
    }
}

// -------------------- MoE weighted reduce --------------------
__global__ void moe_reduce_kernel(const float* __restrict__ Ob,
                                  const float* __restrict__ Wg,
                                  float* __restrict__ X)
{
    int i = blockIdx.x * 256 + threadIdx.x;
    int n = i >> 8;
    float4 acc = ((float4*)X)[i];
#pragma unroll
    for (int e = 0; e < Ee; e++) {
        float w = Wg[n * Ee + e];
        float4 o4 = ((const float4*)Ob)[(long)e * (Nn * Dm / 4) + i];
        acc.x += w * o4.x; acc.y += w * o4.y;
        acc.z += w * o4.z; acc.w += w * o4.w;
    }
    ((float4*)X)[i] = acc;
}

// -------------------- host orchestration --------------------
static inline void launch_gemm(int mode, int bn, const float* A, const float* Bw,
                               float* C, const float* G, int Nrows, int M, int K,
                               int zc, long azs, long bzs, long czs)
{
    dim3 grid(M / bn, Nrows / 128, zc);
    dim3 blk(256);
    if (bn == 128) {
        if (mode == 0)      gemm_tf32<128, 0><<<grid, blk>>>(A, Bw, C, G, K, M, azs, bzs, czs);
        else                gemm_tf32<128, 2><<<grid, blk>>>(A, Bw, C, G, K, M, azs, bzs, czs);
    } else {
        if (mode == 0)      gemm_tf32<64, 0><<<grid, blk>>>(A, Bw, C, G, K, M, azs, bzs, czs);
        else                gemm_tf32<64, 1><<<grid, blk>>>(A, Bw, C, G, K, M, azs, bzs, czs);
    }
}

extern "C" void kernel_launch(void* const* d_in, const int* in_sizes, int n_in,
                              void* d_out, int out_size)
{
    const int*   ids = (const int*)d_in[0];
    const float* enc = (const float*)d_in[1];
    const float* emb = (const float*)d_in[2];
    const float* nw1 = (const float*)d_in[3];
    const float* nw2 = (const float*)d_in[4];
    const float* nw3 = (const float*)d_in[5];
    const float* wqs = (const float*)d_in[6];
    const float* wks = (const float*)d_in[7];
    const float* wvs = (const float*)d_in[8];
    const float* wos = (const float*)d_in[9];
    const float* wqc = (const float*)d_in[10];
    const float* wkc = (const float*)d_in[11];
    const float* wvc = (const float*)d_in[12];
    const float* woc = (const float*)d_in[13];
    const float* rw  = (const float*)d_in[14];
    const float* wg  = (const float*)d_in[15];
    const float* wu  = (const float*)d_in[16];
    const float* wd  = (const float*)d_in[17];
    const float* fnw = (const float*)d_in[18];
    const float* hw  = (const float*)d_in[19];
    float* out = (float*)d_out;

    float *x, *nb, *q, *k, *v, *att, *g, *ob, *wex;
    cudaGetSymbolAddress((void**)&x,   d_x);
    cudaGetSymbolAddress((void**)&nb,  d_nb);
    cudaGetSymbolAddress((void**)&q,   d_q);
    cudaGetSymbolAddress((void**)&k,   d_k);
    cudaGetSymbolAddress((void**)&v,   d_v);
    cudaGetSymbolAddress((void**)&att, d_att);
    cudaGetSymbolAddress((void**)&g,   d_g);
    cudaGetSymbolAddress((void**)&ob,  d_ob);
    cudaGetSymbolAddress((void**)&wex, d_wex);

    const long DD = (long)Dm * Dm;

    embed_kernel<<<Nn * Dm / 4 / 256, 256>>>(ids, emb, x);

    for (int l = 0; l < NLAY; l++) {
        // ---- self attention ----
        rms_kernel<<<Nn, 256>>>(x, nw1 + l * Dm, nb);
        launch_gemm(0, 64, nb, wqs + l * DD, q, nullptr, Nn, Dm, Dm, 1, 0, 0, 0);
        launch_gemm(0, 64, nb, wks + l * DD, k, nullptr, Nn, Dm, Dm, 1, 0, 0, 0);
        launch_gemm(0, 64, nb, wvs + l * DD, v, nullptr, Nn, Dm, Dm, 1, 0, 0, 0);
        attn_kernel<<<dim3(Tt, Hh, Bb), 128>>>(q, k, v, att, Tt, Tt, 1);
        launch_gemm(1, 64, att, wos + l * DD, x, nullptr, Nn, Dm, Dm, 1, 0, 0, 0);

        // ---- cross attention ----
        rms_kernel<<<Nn, 256>>>(x, nw2 + l * Dm, nb);
        launch_gemm(0, 64, nb,  wqc + l * DD, q, nullptr, Nn,  Dm, Dm, 1, 0, 0, 0);
        launch_gemm(0, 128, enc, wkc + l * DD, k, nullptr, NE2, Dm, Dm, 1, 0, 0, 0);
        launch_gemm(0, 128, enc, wvc + l * DD, v, nullptr, NE2, Dm, Dm, 1, 0, 0, 0);
        attn_kernel<<<dim3(Tt, Hh, Bb), 128>>>(q, k, v, att, TEe, TEe, 0);
        launch_gemm(1, 64, att, woc + l * DD, x, nullptr, Nn, Dm, Dm, 1, 0, 0, 0);

        // ---- MoE ----
        rms_kernel<<<Nn, 256>>>(x, nw3 + l * Dm, nb);
        router_kernel<<<Nn, 256>>>(nb, rw + (long)l * Ee * Dm, wex);
        launch_gemm(0, 128, nb, wg + (long)l * Ee * HIDf * Dm, g, nullptr,
                    Nn, HIDf, Dm, Ee, 0, (long)HIDf * Dm, (long)Nn * HIDf);
        launch_gemm(2, 128, nb, wu + (long)l * Ee * HIDf * Dm, g, g,
                    Nn, HIDf, Dm, Ee, 0, (long)HIDf * Dm, (long)Nn * HIDf);
        launch_gemm(0, 128, g, wd + (long)l * Ee * Dm * HIDf, ob, nullptr,
                    Nn, Dm, HIDf, Ee, (long)Nn * HIDf, (long)Dm * HIDf, (long)Nn * Dm);
        moe_reduce_kernel<<<Nn * Dm / 4 / 256, 256>>>(ob, wex, x);
    }

    // ---- final norm + heads ----
    rms_kernel<<<Nn, 256>>>(x, fnw, nb);
    for (int lev = 0; lev < 3; lev++)
        launch_gemm(0, 128, nb, hw + (long)lev * KCB * Dm,
                    out + (long)lev * Nn * KCB, nullptr, Nn, KCB, Dm, 1, 0, 0, 0);
}